// round 1
// baseline (speedup 1.0000x reference)
#include <cuda_runtime.h>
#include <cuda_bf16.h>
#include <math.h>

// ---------------- problem constants ----------------
#define NOPEN 64
#define NNIN  16
#define MAXN  65536            // >= 50000 nodes
#define DTH   0.025f           // dt*H = (1/4)*0.1

// ---------------- device scratch (static, zero-initialized at load) ------
__device__ float g_x[(size_t)MAXN * NOPEN];     // node-major features
__device__ float g_div[(size_t)MAXN * NOPEN];   // node-major divergence accum (kept zeroed)
__device__ float g_dinv[MAXN];
__device__ int   g_deg[MAXN];

// ---------------- degree / norm ----------------
__global__ void deg_init_kernel(int nN) {
    int i = blockIdx.x * blockDim.x + threadIdx.x;
    if (i < nN) g_deg[i] = 1;   // self loop
}

__global__ void deg_count_kernel(const int* __restrict__ jInd, int nE) {
    int i = blockIdx.x * blockDim.x + threadIdx.x;
    if (i < nE) atomicAdd(&g_deg[jInd[i]], 1);
}

__global__ void dinv_kernel(int nN) {
    int i = blockIdx.x * blockDim.x + threadIdx.x;
    if (i < nN) g_dinv[i] = rsqrtf((float)g_deg[i]);
}

// ---------------- x0 = relu(K1Nopen @ xn), stored node-major ----------------
// one warp per node; lane owns outputs {2*lane, 2*lane+1}
__global__ void x0_kernel(const float* __restrict__ xn, const float* __restrict__ K1,
                          int nN) {
    int lane  = threadIdx.x & 31;
    int warp  = (blockIdx.x * blockDim.x + threadIdx.x) >> 5;
    int nwarp = (gridDim.x * blockDim.x) >> 5;
    int o0 = 2 * lane;
    for (int n = warp; n < nN; n += nwarp) {
        float xv = (lane < NNIN) ? xn[(size_t)lane * nN + n] : 0.f;
        float v0 = 0.f, v1 = 0.f;
#pragma unroll
        for (int c = 0; c < NNIN; c++) {
            float xc = __shfl_sync(0xffffffffu, xv, c);
            v0 += __ldg(&K1[(o0)     * NNIN + c]) * xc;
            v1 += __ldg(&K1[(o0 + 1) * NNIN + c]) * xc;
        }
        float2 r;
        r.x = fmaxf(v0, 0.f);
        r.y = fmaxf(v1, 0.f);
        *(float2*)&g_x[(size_t)n * NOPEN + o0] = r;
    }
}

// ---------------- edge kernel: the heavy part ----------------
// Per warp: tile of EPT edges. g tile (64 x EPT) staged in shared, two chained
// 64x64 matvecs amortizing shared KN1 loads over the tile, then vector
// reductions into g_div.
#define WPB 6     // warps per block
#define EPT 16    // edges per warp-tile

__global__ void __launch_bounds__(WPB * 32, 4)
edge_kernel(const int* __restrict__ iInd, const int* __restrict__ jInd,
            const float* __restrict__ KN1w, int nE) {
    // sTp[k*65 + o] = KN1[o][k]   (pitch 65 -> conflict-free both ways)
    __shared__ float sTp[64 * 65];
    __shared__ __align__(16) float sG[WPB][EPT][64];
    __shared__ int   sI[WPB][EPT];
    __shared__ int   sJ[WPB][EPT];
    __shared__ float sW[WPB][EPT];

    for (int idx = threadIdx.x; idx < 64 * 64; idx += blockDim.x) {
        int o = idx >> 6, k = idx & 63;
        sTp[k * 65 + o] = KN1w[idx];
    }
    __syncthreads();

    int lane  = threadIdx.x & 31;
    int ws    = threadIdx.x >> 5;
    int gwarp = blockIdx.x * WPB + ws;
    int nwarp = gridDim.x * WPB;
    int o0 = 2 * lane, o1 = 2 * lane + 1;

    for (long long base = (long long)gwarp * EPT; base < nE;
         base += (long long)nwarp * EPT) {
        // ---- load edge indices + weights (lanes 0..EPT-1) ----
        if (lane < EPT) {
            long long e = base + lane;
            int I = 0, J = 0;
            if (e < (long long)nE) { I = iInd[e]; J = jInd[e]; }
            sI[ws][lane] = I;
            sJ[ws][lane] = J;
            sW[ws][lane] = g_dinv[I] * g_dinv[J];
        }
        __syncwarp();

        // ---- gather g = w*(x[I]-x[J]) into shared tile ----
#pragma unroll
        for (int c = 0; c < EPT; c++) {
            int I = sI[ws][c], J = sJ[ws][c];
            float w = sW[ws][c];
            float2 xi = *(const float2*)&g_x[(size_t)I * NOPEN + o0];
            float2 xj = *(const float2*)&g_x[(size_t)J * NOPEN + o0];
            float2 gv;
            gv.x = (xi.x - xj.x) * w;
            gv.y = (xi.y - xj.y) * w;
            *(float2*)&sG[ws][c][o0] = gv;
        }
        __syncwarp();

        // ---- matvec 1: z = relu(KN1 @ g); z[o] = sum_k KN1[o][k]*g[k] ----
        float zA[EPT], zB[EPT];
#pragma unroll
        for (int c = 0; c < EPT; c++) { zA[c] = 0.f; zB[c] = 0.f; }
#pragma unroll 4
        for (int kk = 0; kk < 64; kk += 4) {
            float a00 = sTp[(kk + 0) * 65 + o0], a01 = sTp[(kk + 0) * 65 + o1];
            float a10 = sTp[(kk + 1) * 65 + o0], a11 = sTp[(kk + 1) * 65 + o1];
            float a20 = sTp[(kk + 2) * 65 + o0], a21 = sTp[(kk + 2) * 65 + o1];
            float a30 = sTp[(kk + 3) * 65 + o0], a31 = sTp[(kk + 3) * 65 + o1];
#pragma unroll
            for (int c = 0; c < EPT; c++) {
                float4 g4 = *(const float4*)&sG[ws][c][kk];
                zA[c] += a00 * g4.x + a10 * g4.y + a20 * g4.z + a30 * g4.w;
                zB[c] += a01 * g4.x + a11 * g4.y + a21 * g4.z + a31 * g4.w;
            }
        }
        __syncwarp();   // everyone done READING sG before overwriting

        // ---- relu, stage z back into shared ----
#pragma unroll
        for (int c = 0; c < EPT; c++) {
            float2 zv;
            zv.x = fmaxf(zA[c], 0.f);
            zv.y = fmaxf(zB[c], 0.f);
            *(float2*)&sG[ws][c][o0] = zv;
        }
        __syncwarp();

        // ---- matvec 2: y[o] = sum_k KN1[k][o]*z[k] = sum_k sTp[o*65+k]*z[k] ----
        float yA[EPT], yB[EPT];
#pragma unroll
        for (int c = 0; c < EPT; c++) { yA[c] = 0.f; yB[c] = 0.f; }
#pragma unroll 4
        for (int kk = 0; kk < 64; kk += 4) {
            float b00 = sTp[o0 * 65 + kk + 0], b01 = sTp[o1 * 65 + kk + 0];
            float b10 = sTp[o0 * 65 + kk + 1], b11 = sTp[o1 * 65 + kk + 1];
            float b20 = sTp[o0 * 65 + kk + 2], b21 = sTp[o1 * 65 + kk + 2];
            float b30 = sTp[o0 * 65 + kk + 3], b31 = sTp[o1 * 65 + kk + 3];
#pragma unroll
            for (int c = 0; c < EPT; c++) {
                float4 z4 = *(const float4*)&sG[ws][c][kk];
                yA[c] += b00 * z4.x + b10 * z4.y + b20 * z4.z + b30 * z4.w;
                yB[c] += b01 * z4.x + b11 * z4.y + b21 * z4.z + b31 * z4.w;
            }
        }

        // ---- scatter: div[I] += w*y ; div[J] -= w*y (vector red, no return) ----
#pragma unroll
        for (int c = 0; c < EPT; c++) {
            int I = sI[ws][c], J = sJ[ws][c];
            float w = sW[ws][c];
            float u0 = yA[c] * w, u1 = yB[c] * w;
            float* pI = &g_div[(size_t)I * NOPEN + o0];
            float* pJ = &g_div[(size_t)J * NOPEN + o0];
            asm volatile("red.global.add.v2.f32 [%0], {%1,%2};"
                         :: "l"(pI), "f"(u0), "f"(u1) : "memory");
            asm volatile("red.global.add.v2.f32 [%0], {%1,%2};"
                         :: "l"(pJ), "f"(-u0), "f"(-u1) : "memory");
        }
        __syncwarp();   // protect sI/sJ/sW/sG before next tile
    }
}

// ---------------- x -= dt*H*div ; div = 0 (keeps div zeroed for next launch) --
__global__ void update_kernel(int total) {
    int i = blockIdx.x * blockDim.x + threadIdx.x;
    if (i < total) {
        g_x[i] = g_x[i] - DTH * g_div[i];
        g_div[i] = 0.f;
    }
}

// ---------------- out = log_softmax(KNclose @ x, over 64 outputs) ----------
__global__ void final_kernel(const float* __restrict__ KC, float* __restrict__ out,
                             int nN) {
    __shared__ float sC[64 * 65];            // sC[i*65+o] = KC[o][i]
    __shared__ __align__(16) float sX[8][64];
    for (int idx = threadIdx.x; idx < 64 * 64; idx += blockDim.x) {
        int o = idx >> 6, i = idx & 63;
        sC[i * 65 + o] = KC[idx];
    }
    __syncthreads();

    int lane  = threadIdx.x & 31;
    int ws    = threadIdx.x >> 5;
    int warp  = (blockIdx.x * blockDim.x + threadIdx.x) >> 5;
    int nwarp = (gridDim.x * blockDim.x) >> 5;
    int o0 = 2 * lane;

    for (int n = warp; n < nN; n += nwarp) {
        *(float2*)&sX[ws][o0] = *(const float2*)&g_x[(size_t)n * NOPEN + o0];
        __syncwarp();
        float v0 = 0.f, v1 = 0.f;
#pragma unroll 8
        for (int i = 0; i < 64; i++) {
            float xi = sX[ws][i];
            v0 += sC[i * 65 + o0] * xi;
            v1 += sC[i * 65 + o0 + 1] * xi;
        }
        float m = fmaxf(v0, v1);
#pragma unroll
        for (int off = 16; off; off >>= 1)
            m = fmaxf(m, __shfl_xor_sync(0xffffffffu, m, off));
        float s = expf(v0 - m) + expf(v1 - m);
#pragma unroll
        for (int off = 16; off; off >>= 1)
            s += __shfl_xor_sync(0xffffffffu, s, off);
        float lse = m + logf(s);
        float2 r;
        r.x = v0 - lse;
        r.y = v1 - lse;
        *(float2*)&out[(size_t)n * NOPEN + o0] = r;
        __syncwarp();
    }
}

// ---------------- launch ----------------
extern "C" void kernel_launch(void* const* d_in, const int* in_sizes, int n_in,
                              void* d_out, int out_size) {
    const float* xn   = (const float*)d_in[0];
    const int*   iInd = (const int*)d_in[1];
    const int*   jInd = (const int*)d_in[2];
    // the scalar 'n_nodes' input may or may not be materialized; detect it
    int base = 3;
    if (n_in >= 7 && in_sizes[3] == 1) base = 4;
    const float* K1  = (const float*)d_in[base];
    const float* KN1 = (const float*)d_in[base + 1];
    const float* KC  = (const float*)d_in[base + 2];

    int nN = in_sizes[0] / NNIN;   // xn is (1, 16, N)
    int nE = in_sizes[1];

    deg_init_kernel<<<(nN + 255) / 256, 256>>>(nN);
    deg_count_kernel<<<(nE + 255) / 256, 256>>>(jInd, nE);
    dinv_kernel<<<(nN + 255) / 256, 256>>>(nN);
    x0_kernel<<<1024, 256>>>(xn, K1, nN);

    int total = nN * NOPEN;
    for (int l = 0; l < 4; l++) {
        edge_kernel<<<1184, WPB * 32>>>(iInd, jInd, KN1, nE);
        update_kernel<<<(total + 255) / 256, 256>>>(total);
    }
    final_kernel<<<1024, 256>>>(KC, (float*)d_out, nN);
}